// round 11
// baseline (speedup 1.0000x reference)
#include <cuda_runtime.h>
#include <cuda_bf16.h>
#include <cstdint>

// 3x3 cross-correlation, 4096x4096 fp32, pad=1, stride=1.
// out[i][j] = sum_{dr,dc} w[dr*3+dc] * x[i+dr-1][j+dc-1] + bias
//
// Consolidated best-of: R6 shape (256-thread CTA, 8 warps x 256w x 8r strips,
// grid 16x64) + exact distance-2 prefetch gating (10 input rows per 8-output
// strip) + __stcs streaming stores + (256,4) launch bounds (<=64 regs,
// 32 warps/SM).

#define N_IMG 4096
#define TW    256
#define RPT   8
#define WARPS 8
#define TILE_H (RPT * WARPS)   // 64 rows per CTA
#define FULLMASK 0xFFFFFFFFu

struct Raw { float4 lo, hi; float e; };

__device__ __forceinline__ Raw fetch_fast(const float* __restrict__ x,
                                          int grow, int c0, int lane)
{
    const float* rowp = x + (size_t)grow * N_IMG;
    Raw r;
    r.lo = *reinterpret_cast<const float4*>(rowp + c0);
    r.hi = *reinterpret_cast<const float4*>(rowp + c0 + 4);
    r.e  = 0.f;
    if (lane == 0)  r.e = rowp[c0 - 1];
    if (lane == 31) r.e = rowp[c0 + 8];
    return r;
}

__device__ __forceinline__ Raw fetch_guard(const float* __restrict__ x,
                                           int grow, int c0, int lane)
{
    Raw r;
    r.lo = make_float4(0.f,0.f,0.f,0.f);
    r.hi = make_float4(0.f,0.f,0.f,0.f);
    r.e  = 0.f;
    if ((unsigned)grow < (unsigned)N_IMG) {   // warp-uniform
        const float* rowp = x + (size_t)grow * N_IMG;
        r.lo = *reinterpret_cast<const float4*>(rowp + c0);
        r.hi = *reinterpret_cast<const float4*>(rowp + c0 + 4);
        if (lane == 0 && c0 > 0)          r.e = rowp[c0 - 1];
        if (lane == 31 && c0 + 8 < N_IMG) r.e = rowp[c0 + 8];
    }
    return r;
}

// raw -> 10-float shifted row (cols c0-1 .. c0+8)
__device__ __forceinline__ void expand(const Raw& q, int lane, float* v)
{
    float lf = __shfl_up_sync(FULLMASK, q.hi.w, 1);
    float rt = __shfl_down_sync(FULLMASK, q.lo.x, 1);
    if (lane == 0)  lf = q.e;
    if (lane == 31) rt = q.e;
    v[0]=lf;     v[1]=q.lo.x; v[2]=q.lo.y; v[3]=q.lo.z; v[4]=q.lo.w;
    v[5]=q.hi.x; v[6]=q.hi.y; v[7]=q.hi.z; v[8]=q.hi.w; v[9]=rt;
}

template<bool GUARD>
__device__ __forceinline__ void do_strip(const float* __restrict__ x,
                                         float* __restrict__ out,
                                         int row0, int tile_x, int lane,
                                         const float* w, float b)
{
    const int c0 = tile_x + lane * 8;
    float r[3][10];
    Raw pfA, pfB;

    if (GUARD) {
        Raw a = fetch_guard(x, row0 - 1, c0, lane);
        Raw q = fetch_guard(x, row0,     c0, lane);
        pfA   = fetch_guard(x, row0 + 1, c0, lane);
        pfB   = fetch_guard(x, row0 + 2, c0, lane);
        expand(a, lane, r[0]);
        expand(q, lane, r[1]);
    } else {
        Raw a = fetch_fast(x, row0 - 1, c0, lane);
        Raw q = fetch_fast(x, row0,     c0, lane);
        pfA   = fetch_fast(x, row0 + 1, c0, lane);
        pfB   = fetch_fast(x, row0 + 2, c0, lane);
        expand(a, lane, r[0]);
        expand(q, lane, r[1]);
    }

    #pragma unroll
    for (int i = 0; i < RPT; i++) {
        // row (row0+i+1) becomes resident
        expand(pfA, lane, r[(i + 2) % 3]);
        pfA = pfB;

        // fetch row (row0+i+3), consumed at iter i+2; gate so exactly
        // RPT+2 input rows are read per strip
        if (i <= RPT - 3) {
            if (GUARD) pfB = fetch_guard(x, row0 + i + 3, c0, lane);
            else       pfB = fetch_fast (x, row0 + i + 3, c0, lane);
        }

        const float* r0 = r[ i      % 3];
        const float* r1 = r[(i + 1) % 3];
        const float* r2 = r[(i + 2) % 3];

        float o[8];
        #pragma unroll
        for (int j = 0; j < 8; j++) {
            float acc = b;
            acc = fmaf(w[0], r0[j    ], acc);
            acc = fmaf(w[1], r0[j + 1], acc);
            acc = fmaf(w[2], r0[j + 2], acc);
            acc = fmaf(w[3], r1[j    ], acc);
            acc = fmaf(w[4], r1[j + 1], acc);
            acc = fmaf(w[5], r1[j + 2], acc);
            acc = fmaf(w[6], r2[j    ], acc);
            acc = fmaf(w[7], r2[j + 1], acc);
            acc = fmaf(w[8], r2[j + 2], acc);
            o[j] = acc;
        }

        float* orow = out + (size_t)(row0 + i) * N_IMG + c0;
        __stcs(reinterpret_cast<float4*>(orow),
               make_float4(o[0], o[1], o[2], o[3]));
        __stcs(reinterpret_cast<float4*>(orow + 4),
               make_float4(o[4], o[5], o[6], o[7]));
    }
}

__global__ __launch_bounds__(256, 4)
void conv3x3_best_kernel(const float* __restrict__ x,
                         const float* __restrict__ w9,
                         const float* __restrict__ bias,
                         float* __restrict__ out)
{
    const int lane   = threadIdx.x & 31;
    const int warp   = threadIdx.x >> 5;
    const int tile_x = blockIdx.x * TW;
    const int row0   = blockIdx.y * TILE_H + warp * RPT;

    float w[9];
    #pragma unroll
    for (int i = 0; i < 9; i++) w[i] = __ldg(&w9[i]);
    const float b = __ldg(&bias[0]);

    const bool guard = (row0 == 0) | (row0 + RPT >= N_IMG) |
                       (tile_x == 0) | (tile_x + TW >= N_IMG);

    if (!guard)
        do_strip<false>(x, out, row0, tile_x, lane, w, b);
    else
        do_strip<true >(x, out, row0, tile_x, lane, w, b);
}

extern "C" void kernel_launch(void* const* d_in, const int* in_sizes, int n_in,
                              void* d_out, int out_size)
{
    const float* x    = (const float*)d_in[0];   // 4096*4096
    const float* w9   = (const float*)d_in[1];   // 9
    const float* bias = (const float*)d_in[2];   // 1
    float* out        = (float*)d_out;           // 4096*4096

    dim3 block(256, 1, 1);
    dim3 grid(N_IMG / TW, N_IMG / TILE_H, 1);    // 16 x 64 = 1024 CTAs
    conv3x3_best_kernel<<<grid, block>>>(x, w9, bias, out);
}